// round 9
// baseline (speedup 1.0000x reference)
#include <cuda_runtime.h>
#include <cstdint>

#define IMG_H 512
#define IMG_W 512
#define N_IMG 16
#define WORDS_PER_ROW 16
#define WORDS_PER_IMG (IMG_H * WORDS_PER_ROW)   // 8192
#define PLANE (IMG_H * IMG_W)
#define N_CHUNK 4
#define CHUNK_SZ 4

__device__ unsigned g_strong[N_IMG * WORDS_PER_IMG];
__device__ unsigned g_weak  [N_IMG * WORDS_PER_IMG];
__device__ unsigned g_edge  [N_IMG * WORDS_PER_IMG];

// ---------------------------------------------------------------------------
// K1: gray -> sobel -> NMS -> strong/weak bitmasks. blockIdx.z = chunk-local img.
// ---------------------------------------------------------------------------
__global__ __launch_bounds__(512, 3) void canny_nms_kernel(const float* __restrict__ x,
                                                           int img_base) {
    const int img = img_base + blockIdx.z;
    const int tx0 = blockIdx.x * 32;
    const int ty0 = blockIdx.y * 64;

    __shared__ float gs[68][37];

    const int tx = threadIdx.x, ty = threadIdx.y;
    const float* xb = x + (size_t)img * 3 * PLANE;

    for (int r = ty; r < 68; r += 16) {
        int gr = min(max(ty0 + r - 2, 0), IMG_H - 1);
        const float* rb = xb + gr * IMG_W;
        {
            int gc = min(max(tx0 + tx - 2, 0), IMG_W - 1);
            float g = __fadd_rn(__fadd_rn(__fmul_rn(0.2989f, __ldg(rb + gc)),
                                          __fmul_rn(0.587f, __ldg(rb + PLANE + gc))),
                                __fmul_rn(0.114f, __ldg(rb + 2 * PLANE + gc)));
            gs[r][tx] = floorf(fminf(fmaxf(g, 0.0f), 255.0f));
        }
        if (tx < 4) {
            int c = 32 + tx;
            int gc = min(max(tx0 + c - 2, 0), IMG_W - 1);
            float g = __fadd_rn(__fadd_rn(__fmul_rn(0.2989f, __ldg(rb + gc)),
                                          __fmul_rn(0.587f, __ldg(rb + PLANE + gc))),
                                __fmul_rn(0.114f, __ldg(rb + 2 * PLANE + gc)));
            gs[r][c] = floorf(fminf(fmaxf(g, 0.0f), 255.0f));
        }
    }
    __syncthreads();

    const int y0 = ty * 4;

    float mag[6];
    unsigned cls = 0;
    {
        float c00 = gs[y0][tx + 1],     c01 = gs[y0][tx + 2],     c02 = gs[y0][tx + 3];
        float c10 = gs[y0 + 1][tx + 1], c11 = gs[y0 + 1][tx + 2], c12 = gs[y0 + 1][tx + 3];
#pragma unroll
        for (int j = 0; j < 6; j++) {
            float c20 = gs[y0 + j + 2][tx + 1];
            float c21 = gs[y0 + j + 2][tx + 2];
            float c22 = gs[y0 + j + 2][tx + 3];
            float gx = (c02 + 2.0f * c12 + c22) - (c00 + 2.0f * c10 + c20);
            float gy = (c20 + 2.0f * c21 + c22) - (c00 + 2.0f * c01 + c02);
            float ax = fabsf(gx), ay = fabsf(gy);
            int gm = ty0 + y0 - 1 + j;
            mag[j] = ((unsigned)gm < (unsigned)IMG_H) ? (ax + ay) : 0.0f;
            if (ay <= 0.4142135623730951f * ax) cls |= 1u << j;
            if (ay >  2.414213562373095f  * ax) cls |= 1u << (8 + j);
            if (gx * gy >= 0.0f)                cls |= 1u << (16 + j);
            c00 = c10; c01 = c11; c02 = c12;
            c10 = c20; c11 = c21; c12 = c22;
        }
    }

    float magH[6];
#pragma unroll
    for (int j = 0; j < 6; j++) magH[j] = 0.0f;
    if (tx == 0 || tx == 31) {
        bool valid = (tx == 0) ? (blockIdx.x > 0) : (blockIdx.x < gridDim.x - 1);
        if (valid) {
            int cb = (tx == 0) ? 0 : 33;
            float c00 = gs[y0][cb],     c01 = gs[y0][cb + 1],     c02 = gs[y0][cb + 2];
            float c10 = gs[y0 + 1][cb], c11 = gs[y0 + 1][cb + 1], c12 = gs[y0 + 1][cb + 2];
#pragma unroll
            for (int j = 0; j < 6; j++) {
                float c20 = gs[y0 + j + 2][cb];
                float c21 = gs[y0 + j + 2][cb + 1];
                float c22 = gs[y0 + j + 2][cb + 2];
                float gx = (c02 + 2.0f * c12 + c22) - (c00 + 2.0f * c10 + c20);
                float gy = (c20 + 2.0f * c21 + c22) - (c00 + 2.0f * c01 + c02);
                int gm = ty0 + y0 - 1 + j;
                if ((unsigned)gm < (unsigned)IMG_H) magH[j] = fabsf(gx) + fabsf(gy);
                c00 = c10; c01 = c11; c02 = c12;
                c10 = c20; c11 = c21; c12 = c22;
            }
        }
    }

    float magL[6], magR[6];
#pragma unroll
    for (int j = 0; j < 6; j++) {
        float l = __shfl_up_sync(0xffffffffu, mag[j], 1);
        float r = __shfl_down_sync(0xffffffffu, mag[j], 1);
        magL[j] = (tx == 0)  ? magH[j] : l;
        magR[j] = (tx == 31) ? magH[j] : r;
    }

#pragma unroll
    for (int k = 0; k < 4; k++) {
        int j = k + 1;
        float m = mag[j];
        bool horiz = (cls >> j) & 1u;
        bool vert  = (cls >> (8 + j)) & 1u;
        bool ssg   = (cls >> (16 + j)) & 1u;
        float n1 = horiz ? magR[j] : (vert ? mag[k]     : (ssg ? magL[k]     : magR[k]));
        float n2 = horiz ? magL[j] : (vert ? mag[k + 2] : (ssg ? magR[k + 2] : magL[k + 2]));
        bool keep = (m > n1) && (m >= n2);
        float nms = keep ? m : 0.0f;

        unsigned sb = __ballot_sync(0xffffffffu, nms > 150.0f);
        unsigned wb = __ballot_sync(0xffffffffu, nms > 50.0f);
        if (tx == 0) {
            int row = ty0 + y0 + k;
            int idx = (img * IMG_H + row) * WORDS_PER_ROW + blockIdx.x;
            g_strong[idx] = sb;
            g_weak[idx]   = wb;
        }
    }
}

// ---------------------------------------------------------------------------
// K2: hysteresis with frontier gating. Thread owns 8-row x 32-col strip.
// chg[tid] marks strips that changed last sweep; a thread recomputes only if
// one of its <=9 input strips changed. Exact same fixed point.
// ---------------------------------------------------------------------------
__device__ __forceinline__ unsigned Hd(unsigned m, unsigned l, unsigned r) {
    return m | (m << 1) | (m >> 1) | (l >> 31) | (r << 31);
}
__device__ __forceinline__ unsigned close_runs(unsigned g, unsigned w) {
    unsigned up = ((w + g) ^ w) & w;
    unsigned rg = __brev(g), rw = __brev(w);
    unsigned dn = __brev(((rw + rg) ^ rw) & rw);
    return g | up | dn;
}

__global__ __launch_bounds__(1024) void hysteresis_kernel(int img_base) {
    const int img = img_base + blockIdx.x;
    __shared__ unsigned cur[WORDS_PER_IMG];   // 32 KB
    __shared__ int chg[1024];                 // 4 KB: per-(rowgroup,col) flag
    const unsigned* wp = g_weak   + img * WORDS_PER_IMG;
    const unsigned* sp = g_strong + img * WORDS_PER_IMG;
    const int tid = threadIdx.x;
    const int w  = tid & 15;
    const int rg = tid >> 4;      // 0..63
    const int r0 = rg << 3;

    unsigned reg[8], wk[8];
#pragma unroll
    for (int i = 0; i < 8; i++) {
        int idx = (r0 + i) * 16 + w;
        reg[i] = sp[idx];
        wk[i]  = wp[idx];
        cur[idx] = reg[i];
    }
    chg[tid] = 1;
    __syncthreads();

    for (;;) {
        // Frontier check: did any of my <=9 input strips change last sweep?
        int need = chg[tid];
        {
            bool wl = (w > 0), wr = (w < 15);
            if (wl) need |= chg[tid - 1];
            if (wr) need |= chg[tid + 1];
            if (rg > 0) {
                need |= chg[tid - 16];
                if (wl) need |= chg[tid - 17];   // up-left
                if (wr) need |= chg[tid - 15];   // up-right
            }
            if (rg < 63) {
                need |= chg[tid + 16];
                if (wl) need |= chg[tid + 15];   // down-left  (FIXED)
                if (wr) need |= chg[tid + 17];   // down-right (FIXED)
            }
        }

        unsigned changed = 0;
        if (need) {
            unsigned lw[10], rw[10];
#pragma unroll
            for (int j = 0; j < 10; j++) {
                int r = r0 - 1 + j;
                bool ok = (r >= 0 && r < IMG_H);
                lw[j] = (ok && w > 0)  ? cur[r * 16 + w - 1] : 0u;
                rw[j] = (ok && w < 15) ? cur[r * 16 + w + 1] : 0u;
            }
            unsigned ab = (r0 > 0)         ? cur[(r0 - 1) * 16 + w] : 0u;
            unsigned bl = (r0 + 8 < IMG_H) ? cur[(r0 + 8) * 16 + w] : 0u;

#pragma unroll
            for (int i = 0; i < 8; i++) {
                unsigned up_row = (i == 0) ? ab : reg[i - 1];
                unsigned dn_row = (i == 7) ? bl : reg[i + 1];
                unsigned dil = Hd(up_row, lw[i], rw[i])
                             | Hd(reg[i], lw[i + 1], rw[i + 1])
                             | Hd(dn_row, lw[i + 2], rw[i + 2]);
                unsigned g = reg[i] | (wk[i] & dil);
                unsigned nv = g ? close_runs(g, wk[i]) : 0u;
                changed |= nv ^ reg[i];
                reg[i] = nv;
            }
#pragma unroll
            for (int i = 7; i >= 0; i--) {
                unsigned up_row = (i == 0) ? ab : reg[i - 1];
                unsigned dn_row = (i == 7) ? bl : reg[i + 1];
                unsigned dil = Hd(up_row, lw[i], rw[i])
                             | Hd(reg[i], lw[i + 1], rw[i + 1])
                             | Hd(dn_row, lw[i + 2], rw[i + 2]);
                unsigned g = reg[i] | (wk[i] & dil);
                unsigned nv = g ? close_runs(g, wk[i]) : 0u;
                changed |= nv ^ reg[i];
                reg[i] = nv;
            }
        }

        __syncthreads();   // all reads of cur/chg complete
        if (changed) {
#pragma unroll
            for (int i = 0; i < 8; i++) cur[(r0 + i) * 16 + w] = reg[i];
        }
        chg[tid] = (changed != 0);
        if (!__syncthreads_or(changed != 0)) break;
    }

    unsigned* ep = g_edge + img * WORDS_PER_IMG;
#pragma unroll
    for (int i = 0; i < 8; i++) ep[(r0 + i) * 16 + w] = reg[i];
}

// ---------------------------------------------------------------------------
// K3: epilogue. blockIdx.y = chunk-local img. Streaming stores.
// ---------------------------------------------------------------------------
__global__ __launch_bounds__(256) void output_kernel(const float* __restrict__ x,
                                                     const float* __restrict__ Wm,
                                                     const float* __restrict__ bias,
                                                     float* __restrict__ out,
                                                     int img_base) {
    __shared__ float Ws[128];
    __shared__ float bs[32];
    const int tid = threadIdx.x;
    if (tid < 128) Ws[tid] = Wm[tid];
    if (tid < 32)  bs[tid] = bias[tid];
    __syncthreads();

    const int img = img_base + blockIdx.y;
    const int pix = (blockIdx.x * 256 + tid) << 2;

    const float* xb = x + (size_t)img * 3 * PLANE;
    float4 x0 = __ldg((const float4*)(xb + pix));
    float4 x1 = __ldg((const float4*)(xb + PLANE + pix));
    float4 x2 = __ldg((const float4*)(xb + 2 * PLANE + pix));

    unsigned ew = g_edge[img * WORDS_PER_IMG + (pix >> 5)];
    int sh = pix & 31;
    float e0 = ((ew >> (sh    )) & 1u) ? 255.0f : 0.0f;
    float e1 = ((ew >> (sh + 1)) & 1u) ? 255.0f : 0.0f;
    float e2 = ((ew >> (sh + 2)) & 1u) ? 255.0f : 0.0f;
    float e3 = ((ew >> (sh + 3)) & 1u) ? 255.0f : 0.0f;

    float* ob = out + (size_t)img * 32 * PLANE + pix;
#pragma unroll 8
    for (int o = 0; o < 32; o++) {
        float w0 = Ws[4 * o], w1 = Ws[4 * o + 1], w2 = Ws[4 * o + 2], w3 = Ws[4 * o + 3];
        float bb = bs[o];
        float4 v;
        v.x = fmaxf(fmaf(w0, x0.x, fmaf(w1, x1.x, fmaf(w2, x2.x, fmaf(w3, e0, bb)))), 0.0f);
        v.y = fmaxf(fmaf(w0, x0.y, fmaf(w1, x1.y, fmaf(w2, x2.y, fmaf(w3, e1, bb)))), 0.0f);
        v.z = fmaxf(fmaf(w0, x0.z, fmaf(w1, x1.z, fmaf(w2, x2.z, fmaf(w3, e2, bb)))), 0.0f);
        v.w = fmaxf(fmaf(w0, x0.w, fmaf(w1, x1.w, fmaf(w2, x2.w, fmaf(w3, e3, bb)))), 0.0f);
        __stcs((float4*)(ob + (size_t)o * PLANE), v);
    }
}

// ---------------------------------------------------------------------------
// Pipeline: s1 runs K1[c]->K2[c] (compute/latency-bound); stream0 runs K3[c]
// gated on e2[c]. K1/K2 of chunk c+1 overlaps K3 of chunk c.
// Exactly one extra stream (mem-checker budget, proven in R5).
// ---------------------------------------------------------------------------
extern "C" void kernel_launch(void* const* d_in, const int* in_sizes, int n_in,
                              void* d_out, int out_size) {
    (void)in_sizes; (void)n_in; (void)out_size;
    const float* x  = (const float*)d_in[0];
    const float* Wm = (const float*)d_in[1];
    const float* b  = (const float*)d_in[2];
    float* out = (float*)d_out;

    static cudaStream_t s1 = nullptr;
    static cudaEvent_t root = nullptr;
    static cudaEvent_t e2[N_CHUNK];
    if (s1 == nullptr) {
        cudaStreamCreateWithFlags(&s1, cudaStreamNonBlocking);
        cudaEventCreateWithFlags(&root, cudaEventDisableTiming);
        for (int c = 0; c < N_CHUNK; c++)
            cudaEventCreateWithFlags(&e2[c], cudaEventDisableTiming);
    }

    cudaEventRecord(root, 0);
    cudaStreamWaitEvent(s1, root, 0);

    dim3 b1(32, 16);
    for (int c = 0; c < N_CHUNK; c++) {
        dim3 g1(IMG_W / 32, IMG_H / 64, CHUNK_SZ);
        canny_nms_kernel<<<g1, b1, 0, s1>>>(x, c * CHUNK_SZ);
        hysteresis_kernel<<<CHUNK_SZ, 1024, 0, s1>>>(c * CHUNK_SZ);
        cudaEventRecord(e2[c], s1);
    }

    for (int c = 0; c < N_CHUNK; c++) {
        cudaStreamWaitEvent(0, e2[c], 0);
        dim3 g3(PLANE / 4 / 256, CHUNK_SZ);
        output_kernel<<<g3, 256>>>(x, Wm, b, out, c * CHUNK_SZ);
    }
}

// round 10
// speedup vs baseline: 1.1543x; 1.1543x over previous
#include <cuda_runtime.h>
#include <cstdint>

#define IMG_H 512
#define IMG_W 512
#define N_IMG 16
#define WORDS_PER_ROW 16
#define WORDS_PER_IMG (IMG_H * WORDS_PER_ROW)   // 8192
#define PLANE (IMG_H * IMG_W)

__device__ unsigned g_strong[N_IMG * WORDS_PER_IMG];
__device__ unsigned g_weak  [N_IMG * WORDS_PER_IMG];
__device__ unsigned g_edge  [N_IMG * WORDS_PER_IMG];

// ---------------------------------------------------------------------------
// K1: gray -> sobel -> NMS -> strong/weak bitmasks. Batched over all images.
// Tile 32 wide x 64 tall, blockDim (32,16): thread = (column, 4-row strip).
// ---------------------------------------------------------------------------
__global__ __launch_bounds__(512, 3) void canny_nms_kernel(const float* __restrict__ x) {
    const int img = blockIdx.z;
    const int tx0 = blockIdx.x * 32;
    const int ty0 = blockIdx.y * 64;

    __shared__ float gs[68][37];

    const int tx = threadIdx.x, ty = threadIdx.y;
    const int tid = ty * 32 + tx;
    const float* xb = x + (size_t)img * 3 * PLANE;

    // Phase 1: gray 68x36 (edge-clamped), flat balanced loop (no per-warp tail)
    for (int i = tid; i < 68 * 36; i += 512) {
        int r = i / 36, c = i - r * 36;
        int gr = min(max(ty0 + r - 2, 0), IMG_H - 1);
        int gc = min(max(tx0 + c - 2, 0), IMG_W - 1);
        const float* p = xb + gr * IMG_W + gc;
        float g = __fadd_rn(__fadd_rn(__fmul_rn(0.2989f, __ldg(p)),
                                      __fmul_rn(0.587f, __ldg(p + PLANE))),
                            __fmul_rn(0.114f, __ldg(p + 2 * PLANE)));
        gs[r][c] = floorf(fminf(fmaxf(g, 0.0f), 255.0f));
    }
    __syncthreads();

    const int y0 = ty * 4;

    // Phase 2: own-column mag rows j=0..5 (global row ty0+y0-1+j)
    float mag[6];
    unsigned cls = 0;
    {
        float c00 = gs[y0][tx + 1],     c01 = gs[y0][tx + 2],     c02 = gs[y0][tx + 3];
        float c10 = gs[y0 + 1][tx + 1], c11 = gs[y0 + 1][tx + 2], c12 = gs[y0 + 1][tx + 3];
#pragma unroll
        for (int j = 0; j < 6; j++) {
            float c20 = gs[y0 + j + 2][tx + 1];
            float c21 = gs[y0 + j + 2][tx + 2];
            float c22 = gs[y0 + j + 2][tx + 3];
            float gx = (c02 + 2.0f * c12 + c22) - (c00 + 2.0f * c10 + c20);
            float gy = (c20 + 2.0f * c21 + c22) - (c00 + 2.0f * c01 + c02);
            float ax = fabsf(gx), ay = fabsf(gy);
            int gm = ty0 + y0 - 1 + j;
            mag[j] = ((unsigned)gm < (unsigned)IMG_H) ? (ax + ay) : 0.0f;
            if (ay <= 0.4142135623730951f * ax) cls |= 1u << j;
            if (ay >  2.414213562373095f  * ax) cls |= 1u << (8 + j);
            if (gx * gy >= 0.0f)                cls |= 1u << (16 + j);
            c00 = c10; c01 = c11; c02 = c12;
            c10 = c20; c11 = c21; c12 = c22;
        }
    }

    // Halo columns (lanes 0/31)
    float magH[6];
#pragma unroll
    for (int j = 0; j < 6; j++) magH[j] = 0.0f;
    if (tx == 0 || tx == 31) {
        bool valid = (tx == 0) ? (blockIdx.x > 0) : (blockIdx.x < gridDim.x - 1);
        if (valid) {
            int cb = (tx == 0) ? 0 : 33;
            float c00 = gs[y0][cb],     c01 = gs[y0][cb + 1],     c02 = gs[y0][cb + 2];
            float c10 = gs[y0 + 1][cb], c11 = gs[y0 + 1][cb + 1], c12 = gs[y0 + 1][cb + 2];
#pragma unroll
            for (int j = 0; j < 6; j++) {
                float c20 = gs[y0 + j + 2][cb];
                float c21 = gs[y0 + j + 2][cb + 1];
                float c22 = gs[y0 + j + 2][cb + 2];
                float gx = (c02 + 2.0f * c12 + c22) - (c00 + 2.0f * c10 + c20);
                float gy = (c20 + 2.0f * c21 + c22) - (c00 + 2.0f * c01 + c02);
                int gm = ty0 + y0 - 1 + j;
                if ((unsigned)gm < (unsigned)IMG_H) magH[j] = fabsf(gx) + fabsf(gy);
                c00 = c10; c01 = c11; c02 = c12;
                c10 = c20; c11 = c21; c12 = c22;
            }
        }
    }

    float magL[6], magR[6];
#pragma unroll
    for (int j = 0; j < 6; j++) {
        float l = __shfl_up_sync(0xffffffffu, mag[j], 1);
        float r = __shfl_down_sync(0xffffffffu, mag[j], 1);
        magL[j] = (tx == 0)  ? magH[j] : l;
        magR[j] = (tx == 31) ? magH[j] : r;
    }

#pragma unroll
    for (int k = 0; k < 4; k++) {
        int j = k + 1;
        float m = mag[j];
        bool horiz = (cls >> j) & 1u;
        bool vert  = (cls >> (8 + j)) & 1u;
        bool ssg   = (cls >> (16 + j)) & 1u;
        float n1 = horiz ? magR[j] : (vert ? mag[k]     : (ssg ? magL[k]     : magR[k]));
        float n2 = horiz ? magL[j] : (vert ? mag[k + 2] : (ssg ? magR[k + 2] : magL[k + 2]));
        bool keep = (m > n1) && (m >= n2);
        float nms = keep ? m : 0.0f;

        unsigned sb = __ballot_sync(0xffffffffu, nms > 150.0f);
        unsigned wb = __ballot_sync(0xffffffffu, nms > 50.0f);
        if (tx == 0) {
            int row = ty0 + y0 + k;
            int idx = (img * IMG_H + row) * WORDS_PER_ROW + blockIdx.x;
            g_strong[idx] = sb;
            g_weak[idx]   = wb;
        }
    }
}

// ---------------------------------------------------------------------------
// K2: hysteresis, batched: one block per image, frontier-gated sweeps.
// ---------------------------------------------------------------------------
__device__ __forceinline__ unsigned Hd(unsigned m, unsigned l, unsigned r) {
    return m | (m << 1) | (m >> 1) | (l >> 31) | (r << 31);
}
__device__ __forceinline__ unsigned close_runs(unsigned g, unsigned w) {
    unsigned up = ((w + g) ^ w) & w;
    unsigned rg = __brev(g), rw = __brev(w);
    unsigned dn = __brev(((rw + rg) ^ rw) & rw);
    return g | up | dn;
}

__global__ __launch_bounds__(1024) void hysteresis_kernel() {
    const int img = blockIdx.x;
    __shared__ unsigned cur[WORDS_PER_IMG];   // 32 KB
    __shared__ int chg[1024];                 // 4 KB
    const unsigned* wp = g_weak   + img * WORDS_PER_IMG;
    const unsigned* sp = g_strong + img * WORDS_PER_IMG;
    const int tid = threadIdx.x;
    const int w  = tid & 15;
    const int rg = tid >> 4;
    const int r0 = rg << 3;

    unsigned reg[8], wk[8];
#pragma unroll
    for (int i = 0; i < 8; i++) {
        int idx = (r0 + i) * 16 + w;
        reg[i] = sp[idx];
        wk[i]  = wp[idx];
        cur[idx] = reg[i];
    }
    chg[tid] = 1;
    __syncthreads();

    for (;;) {
        int need = chg[tid];
        {
            bool wl = (w > 0), wr = (w < 15);
            if (wl) need |= chg[tid - 1];
            if (wr) need |= chg[tid + 1];
            if (rg > 0) {
                need |= chg[tid - 16];
                if (wl) need |= chg[tid - 17];
                if (wr) need |= chg[tid - 15];
            }
            if (rg < 63) {
                need |= chg[tid + 16];
                if (wl) need |= chg[tid + 15];
                if (wr) need |= chg[tid + 17];
            }
        }

        unsigned changed = 0;
        if (need) {
            unsigned lw[10], rw[10];
#pragma unroll
            for (int j = 0; j < 10; j++) {
                int r = r0 - 1 + j;
                bool ok = (r >= 0 && r < IMG_H);
                lw[j] = (ok && w > 0)  ? cur[r * 16 + w - 1] : 0u;
                rw[j] = (ok && w < 15) ? cur[r * 16 + w + 1] : 0u;
            }
            unsigned ab = (r0 > 0)         ? cur[(r0 - 1) * 16 + w] : 0u;
            unsigned bl = (r0 + 8 < IMG_H) ? cur[(r0 + 8) * 16 + w] : 0u;

#pragma unroll
            for (int i = 0; i < 8; i++) {
                unsigned up_row = (i == 0) ? ab : reg[i - 1];
                unsigned dn_row = (i == 7) ? bl : reg[i + 1];
                unsigned dil = Hd(up_row, lw[i], rw[i])
                             | Hd(reg[i], lw[i + 1], rw[i + 1])
                             | Hd(dn_row, lw[i + 2], rw[i + 2]);
                unsigned g = reg[i] | (wk[i] & dil);
                unsigned nv = g ? close_runs(g, wk[i]) : 0u;
                changed |= nv ^ reg[i];
                reg[i] = nv;
            }
#pragma unroll
            for (int i = 7; i >= 0; i--) {
                unsigned up_row = (i == 0) ? ab : reg[i - 1];
                unsigned dn_row = (i == 7) ? bl : reg[i + 1];
                unsigned dil = Hd(up_row, lw[i], rw[i])
                             | Hd(reg[i], lw[i + 1], rw[i + 1])
                             | Hd(dn_row, lw[i + 2], rw[i + 2]);
                unsigned g = reg[i] | (wk[i] & dil);
                unsigned nv = g ? close_runs(g, wk[i]) : 0u;
                changed |= nv ^ reg[i];
                reg[i] = nv;
            }
        }

        __syncthreads();
        if (changed) {
#pragma unroll
            for (int i = 0; i < 8; i++) cur[(r0 + i) * 16 + w] = reg[i];
        }
        chg[tid] = (changed != 0);
        if (!__syncthreads_or(changed != 0)) break;
    }

    unsigned* ep = g_edge + img * WORDS_PER_IMG;
#pragma unroll
    for (int i = 0; i < 8; i++) ep[(r0 + i) * 16 + w] = reg[i];
}

// ---------------------------------------------------------------------------
// K3: epilogue. PDL: x loads issue BEFORE griddepcontrol.wait (overlap with K2);
// g_edge is only read after the wait. Streaming stores.
// ---------------------------------------------------------------------------
__global__ __launch_bounds__(256) void output_kernel(const float* __restrict__ x,
                                                     const float* __restrict__ Wm,
                                                     const float* __restrict__ bias,
                                                     float* __restrict__ out) {
    __shared__ float Ws[128];
    __shared__ float bs[32];
    const int tid = threadIdx.x;
    if (tid < 128) Ws[tid] = Wm[tid];
    if (tid < 32)  bs[tid] = bias[tid];

    const long gt  = (long)blockIdx.x * blockDim.x + tid;
    const int img  = (int)(gt >> 16);
    const int pix  = ((int)gt & 65535) << 2;

    // Pre-dependency phase: pull the 50 MB of x while K2 is still running.
    const float* xb = x + (size_t)img * 3 * PLANE;
    float4 x0 = __ldg((const float4*)(xb + pix));
    float4 x1 = __ldg((const float4*)(xb + PLANE + pix));
    float4 x2 = __ldg((const float4*)(xb + 2 * PLANE + pix));
    __syncthreads();   // Ws/bs ready

    // Wait for primary (K2) completion => g_edge visible.
    asm volatile("griddepcontrol.wait;" ::: "memory");

    unsigned ew = g_edge[img * WORDS_PER_IMG + (pix >> 5)];
    int sh = pix & 31;
    float e0 = ((ew >> (sh    )) & 1u) ? 255.0f : 0.0f;
    float e1 = ((ew >> (sh + 1)) & 1u) ? 255.0f : 0.0f;
    float e2 = ((ew >> (sh + 2)) & 1u) ? 255.0f : 0.0f;
    float e3 = ((ew >> (sh + 3)) & 1u) ? 255.0f : 0.0f;

    float* ob = out + (size_t)img * 32 * PLANE + pix;
#pragma unroll 8
    for (int o = 0; o < 32; o++) {
        float w0 = Ws[4 * o], w1 = Ws[4 * o + 1], w2 = Ws[4 * o + 2], w3 = Ws[4 * o + 3];
        float bb = bs[o];
        float4 v;
        v.x = fmaxf(fmaf(w0, x0.x, fmaf(w1, x1.x, fmaf(w2, x2.x, fmaf(w3, e0, bb)))), 0.0f);
        v.y = fmaxf(fmaf(w0, x0.y, fmaf(w1, x1.y, fmaf(w2, x2.y, fmaf(w3, e1, bb)))), 0.0f);
        v.z = fmaxf(fmaf(w0, x0.z, fmaf(w1, x1.z, fmaf(w2, x2.z, fmaf(w3, e2, bb)))), 0.0f);
        v.w = fmaxf(fmaf(w0, x0.w, fmaf(w1, x1.w, fmaf(w2, x2.w, fmaf(w3, e3, bb)))), 0.0f);
        __stcs((float4*)(ob + (size_t)o * PLANE), v);
    }
}

// ---------------------------------------------------------------------------
// Serial stream; K3 launched with Programmatic Stream Serialization so its
// load phase overlaps K2. No extra streams, no events.
// ---------------------------------------------------------------------------
extern "C" void kernel_launch(void* const* d_in, const int* in_sizes, int n_in,
                              void* d_out, int out_size) {
    (void)in_sizes; (void)n_in; (void)out_size;
    const float* x  = (const float*)d_in[0];
    const float* Wm = (const float*)d_in[1];
    const float* b  = (const float*)d_in[2];
    float* out = (float*)d_out;

    dim3 b1(32, 16), g1(IMG_W / 32, IMG_H / 64, N_IMG);
    canny_nms_kernel<<<g1, b1>>>(x);

    hysteresis_kernel<<<N_IMG, 1024>>>();

    cudaLaunchConfig_t cfg = {};
    cfg.gridDim  = dim3(N_IMG * PLANE / 4 / 256, 1, 1);
    cfg.blockDim = dim3(256, 1, 1);
    cfg.dynamicSmemBytes = 0;
    cfg.stream = 0;
    cudaLaunchAttribute attrs[1];
    attrs[0].id = cudaLaunchAttributeProgrammaticStreamSerialization;
    attrs[0].val.programmaticStreamSerializationAllowed = 1;
    cfg.attrs = attrs;
    cfg.numAttrs = 1;
    cudaLaunchKernelEx(&cfg, output_kernel, x, Wm, b, out);
}